// round 14
// baseline (speedup 1.0000x reference)
#include <cuda_runtime.h>
#include <cuda_fp16.h>
#include <math.h>

// ---------------------------------------------------------------------------
// Problem constants
// ---------------------------------------------------------------------------
#define NSAMP   32
#define NIMG    1280          // 640 RGB + 640 depth images of [3,224,224]
#define IMG_HALF 640
#define IMG_ELEMS (3*224*224)
#define CH_ELEMS  (224*224)

// per-image 6-float backbone features: [0..640) rgb, [640..1280) depth
__device__ float g_feats[NIMG * 6];

struct BBParams {
    const float* nodes;
    const float* depths;
    const float* c1w;  const float* c1b;  const float* c2w;  const float* c2b;
    const float* lw;   const float* lb;
    const float* dc1w; const float* dc1b; const float* dc2w; const float* dc2b;
    const float* dlw;  const float* dlb;
};

// ---------------------------------------------------------------------------
// Dynamic shared-memory layout — 12064 floats + 4218 halves = 56692 B
// (<= 57344 B so 4 CTAs/SM fit in 228 KB)
// ---------------------------------------------------------------------------
#define STRIP_ROW 228                 // 224 cols + 4 pad
#define STRIP_CH  (7*STRIP_ROW)       // 7 input rows per pool row
#define STRIP_SZ  (3*STRIP_CH)        // 4788
#define SM_STRIP0 0
#define SM_STRIP1 4788
#define CB_ROW    112
#define CB_CH     (3*CB_ROW)          // 3 conv rows per pool row
#define SM_CONV0  9576                // 1008 floats
#define SM_CONV1  10584               // 1008 floats
#define SM_C2     11592               // 324 floats
#define SM_V      11916               // 36 floats
#define SM_W      11952               // 112 weight floats (w1,b1,w2,b2)
#define SM_F32    12064               // end of float region
// fp16 'inter' buffer: 3*37*38 = 4218 halves placed at sm + SM_F32
#define IN_ROW    38
#define IN_CH     (37*IN_ROW)
#define SMEM_BYTES (SM_F32*4 + IN_CH*3*2 + 4)   // 56696 B

// Bank-conflict swizzle for the strip: logical word w within a row maps to
// physical word w ^ (((w>>5)&1)<<2). Applied identically at store and load.
__device__ __forceinline__ int strip_sw(int w) {
    return w ^ (((w >> 5) & 1) << 2);
}

__device__ __forceinline__ void cp_async16(float* smem_dst, const float* gsrc) {
    unsigned sa = (unsigned)__cvta_generic_to_shared(smem_dst);
    asm volatile("cp.async.cg.shared.global [%0], [%1], 16;" :: "r"(sa), "l"(gsrc));
}
__device__ __forceinline__ void cp_async_commit() {
    asm volatile("cp.async.commit_group;");
}
__device__ __forceinline__ void cp_async_wait_all() {
    asm volatile("cp.async.wait_group 0;");
}

// weight smem sub-offsets (relative to SM_W)
//   w1: [0,81)  b1: [81,84)  w2: [84,111)  b2: [111]

__global__ __launch_bounds__(256, 4)
void backbone_kernel(BBParams P)
{
    extern __shared__ __align__(16) float sm[];
    __half* ih = (__half*)(sm + SM_F32);

    const int img = blockIdx.x;
    const int tid = threadIdx.x;
    const bool rgb = (img < IMG_HALF);
    const int local = rgb ? img : (img - IMG_HALF);
    const float* input = (rgb ? P.nodes : P.depths) + (size_t)local * IMG_ELEMS;

    // ---- prologue: weights + strip(0) load (all threads), single barrier ----
    {
        const float* w1 = rgb ? P.c1w : P.dc1w;
        const float* b1 = rgb ? P.c1b : P.dc1b;
        const float* w2 = rgb ? P.c2w : P.dc2w;
        const float* b2 = rgb ? P.c2b : P.dc2b;
        float* ws = sm + SM_W;
        if (tid < 81)  ws[tid]       = __ldg(w1 + tid);
        if (tid < 3)   ws[81 + tid]  = __ldg(b1 + tid);
        if (tid < 27)  ws[84 + tid]  = __ldg(w2 + tid);
        if (tid == 0)  ws[111]       = __ldg(b2);

        for (int i = tid; i < 3 * 7 * 56; i += 256) {
            const int ch  = i / 392;
            const int rem = i - ch * 392;
            const int r   = rem / 56;
            const int c4  = rem - r * 56;
            cp_async16(sm + SM_STRIP0 + ch * STRIP_CH + r * STRIP_ROW + strip_sw(4 * c4),
                       input + ch * CH_ELEMS + r * 224 + 4 * c4);
        }
        cp_async_commit();
        cp_async_wait_all();
    }
    __syncthreads();

    // ---- stage 1 pipeline: warps 0-2 conv(p); warps 3-7 load(p+1) + pool(p-1)
    for (int p = 0; p < 37; ++p) {
        const float* strip = sm + ((p & 1) ? SM_STRIP1 : SM_STRIP0);
        float*       conv  = sm + ((p & 1) ? SM_CONV1  : SM_CONV0);

        if (tid < 96) {
            // conv1: one warp per conv row; each lane 4 cols x 3 out channels
            const int crow = tid >> 5;
            const int lane = tid & 31;
            const float* ws = sm + SM_W;
            const float b0 = ws[81], b1 = ws[82], b2 = ws[83];
            float4 a0 = make_float4(b0, b0, b0, b0);
            float4 a1 = make_float4(b1, b1, b1, b1);
            float4 a2 = make_float4(b2, b2, b2, b2);

            const int s4 = ((lane >> 2) & 1) << 2;
            const int wA = (8 * lane) ^ s4;
            const int wB = (8 * lane + 4) ^ s4;
            const int wC = (8 * lane + 8) ^ ((((8 * lane + 8) >> 5) & 1) << 2);

            #pragma unroll
            for (int ci = 0; ci < 3; ++ci) {
                const float* sp = strip + ci * STRIP_CH + 2 * crow * STRIP_ROW;
                #pragma unroll
                for (int ky = 0; ky < 3; ++ky) {
                    const float* rp = sp + ky * STRIP_ROW;
                    float4 A = *(const float4*)(rp + wA);
                    float4 B = *(const float4*)(rp + wB);
                    float s8 = rp[wC];

                    const float* wp = ws + ci * 9 + ky * 3;
                    {
                        float u = wp[0], v = wp[1], w = wp[2];
                        a0.x = fmaf(u, A.x, a0.x); a0.x = fmaf(v, A.y, a0.x); a0.x = fmaf(w, A.z, a0.x);
                        a0.y = fmaf(u, A.z, a0.y); a0.y = fmaf(v, A.w, a0.y); a0.y = fmaf(w, B.x, a0.y);
                        a0.z = fmaf(u, B.x, a0.z); a0.z = fmaf(v, B.y, a0.z); a0.z = fmaf(w, B.z, a0.z);
                        a0.w = fmaf(u, B.z, a0.w); a0.w = fmaf(v, B.w, a0.w); a0.w = fmaf(w, s8,  a0.w);
                    }
                    {
                        float u = wp[27], v = wp[28], w = wp[29];
                        a1.x = fmaf(u, A.x, a1.x); a1.x = fmaf(v, A.y, a1.x); a1.x = fmaf(w, A.z, a1.x);
                        a1.y = fmaf(u, A.z, a1.y); a1.y = fmaf(v, A.w, a1.y); a1.y = fmaf(w, B.x, a1.y);
                        a1.z = fmaf(u, B.x, a1.z); a1.z = fmaf(v, B.y, a1.z); a1.z = fmaf(w, B.z, a1.z);
                        a1.w = fmaf(u, B.z, a1.w); a1.w = fmaf(v, B.w, a1.w); a1.w = fmaf(w, s8,  a1.w);
                    }
                    {
                        float u = wp[54], v = wp[55], w = wp[56];
                        a2.x = fmaf(u, A.x, a2.x); a2.x = fmaf(v, A.y, a2.x); a2.x = fmaf(w, A.z, a2.x);
                        a2.y = fmaf(u, A.z, a2.y); a2.y = fmaf(v, A.w, a2.y); a2.y = fmaf(w, B.x, a2.y);
                        a2.z = fmaf(u, B.x, a2.z); a2.z = fmaf(v, B.y, a2.z); a2.z = fmaf(w, B.z, a2.z);
                        a2.w = fmaf(u, B.z, a2.w); a2.w = fmaf(v, B.w, a2.w); a2.w = fmaf(w, s8,  a2.w);
                    }
                }
            }
            if (lane < 28) {
                float* ob = conv + crow * CB_ROW + 4 * lane;
                *(float4*)(ob)             = a0;
                *(float4*)(ob + CB_CH)     = a1;
                *(float4*)(ob + 2 * CB_CH) = a2;
            }
        } else {
            const int lt = tid - 96;               // 0..159
            // prefetch strip(p+1) into the other buffer (fire-and-forget)
            if (p < 36) {
                const int S = 6 * (p + 1);
                float* dst = sm + ((p & 1) ? SM_STRIP0 : SM_STRIP1);
                for (int i = lt; i < 3 * 7 * 56; i += 160) {
                    const int ch  = i / 392;
                    const int rem = i - ch * 392;
                    const int r   = rem / 56;
                    const int c4  = rem - r * 56;
                    cp_async16(dst + ch * STRIP_CH + r * STRIP_ROW + strip_sw(4 * c4),
                               input + ch * CH_ELEMS + (S + r) * 224 + 4 * c4);
                }
                cp_async_commit();
            }
            // pool 3x3 s3 + relu of previous pool row
            if (p > 0 && lt < 111) {
                const int pp = p - 1;
                const int pc = lt % 37;
                const int ch = lt / 37;
                const float* cb = sm + ((pp & 1) ? SM_CONV1 : SM_CONV0) +
                                  ch * CB_CH + 3 * pc;
                float m = cb[0];
                #pragma unroll
                for (int ky = 0; ky < 3; ++ky)
                    #pragma unroll
                    for (int kx = 0; kx < 3; ++kx)
                        m = fmaxf(m, cb[ky * CB_ROW + kx]);
                ih[ch * IN_CH + pp * IN_ROW + pc] = __float2half(fmaxf(m, 0.0f));
            }
            if (p < 36) cp_async_wait_all();
        }
        __syncthreads();
    }

    // final pool row (p = 36, convbuf parity 0)
    if (tid < 111) {
        const int pc = tid % 37;
        const int ch = tid / 37;
        const float* cb = sm + SM_CONV0 + ch * CB_CH + 3 * pc;
        float m = cb[0];
        #pragma unroll
        for (int ky = 0; ky < 3; ++ky)
            #pragma unroll
            for (int kx = 0; kx < 3; ++kx)
                m = fmaxf(m, cb[ky * CB_ROW + kx]);
        ih[ch * IN_CH + 36 * IN_ROW + pc] = __float2half(fmaxf(m, 0.0f));
    }
    __syncthreads();

    // ---- stage 2: conv2(3->1, 3x3, s2): 18x18 outputs ----
    {
        const float* ws = sm + SM_W;
        for (int t = tid; t < 324; t += 256) {
            const int r = t / 18, c = t % 18;
            float acc = ws[111];
            const __half* ip = ih + (2 * r) * IN_ROW + 2 * c;
            #pragma unroll
            for (int ci = 0; ci < 3; ++ci)
                #pragma unroll
                for (int ky = 0; ky < 3; ++ky)
                    #pragma unroll
                    for (int kx = 0; kx < 3; ++kx)
                        acc = fmaf(ws[84 + ci*9 + ky*3 + kx],
                                   __half2float(ip[ci * IN_CH + ky * IN_ROW + kx]), acc);
            sm[SM_C2 + t] = acc;
        }
    }
    __syncthreads();
    // pool 3x3 s3 + relu -> 6x6 = 36 values
    if (tid < 36) {
        const int y = tid / 6, x = tid % 6;
        const float* cb = sm + SM_C2 + (3 * y) * 18 + 3 * x;
        float m = cb[0];
        #pragma unroll
        for (int ky = 0; ky < 3; ++ky)
            #pragma unroll
            for (int kx = 0; kx < 3; ++kx)
                m = fmaxf(m, cb[ky * 18 + kx]);
        sm[SM_V + tid] = fmaxf(m, 0.0f);
    }
    __syncthreads();
    // linear 36 -> 6 (weights straight from global; L2-resident)
    if (tid < 6) {
        const float* lw = rgb ? P.lw : P.dlw;
        const float* lb = rgb ? P.lb : P.dlb;
        float acc = __ldg(lb + tid);
        #pragma unroll
        for (int j = 0; j < 36; ++j)
            acc = fmaf(sm[SM_V + j], __ldg(lw + j * 6 + tid), acc);
        g_feats[img * 6 + tid] = acc;
    }
}

// ---------------------------------------------------------------------------
// Head: message passing + concat + MLP (360->180->60->6). One CTA per sample.
// ---------------------------------------------------------------------------
__global__ __launch_bounds__(512)
void head_kernel(const float* __restrict__ pos, const float* __restrict__ att,
                 const float* __restrict__ fmw, const float* __restrict__ fmb,
                 const float* __restrict__ lmw, const float* __restrict__ lmb,
                 const float* __restrict__ o1w, const float* __restrict__ o1b,
                 const float* __restrict__ o2w, const float* __restrict__ o2b,
                 const float* __restrict__ o3w, const float* __restrict__ o3b,
                 float* __restrict__ out)
{
    __shared__ float pos_s[120], pm[120], pu[120], feat[360];
    __shared__ float p1[360];          // layer-1 partials (2-way k-split)
    __shared__ float h1[180];
    __shared__ float p2[240];          // layer-2 partials (4-way k-split)
    __shared__ float h2[60];
    __shared__ float fmw_s[36], fmb_s[6], lmw_s[36], lmb_s[6];

    const int b = blockIdx.x;
    const int t = threadIdx.x;

    if (t < 120) pos_s[t] = __ldg(pos + b * 120 + t);
    if (t < 36) { fmw_s[t] = __ldg(fmw + t); lmw_s[t] = __ldg(lmw + t); }
    if (t < 6)  { fmb_s[t] = __ldg(fmb + t); lmb_s[t] = __ldg(lmb + t); }
    __syncthreads();

    // per-frame messages pm[f,m,d] = pos @ fmw + fmb
    if (t < 120) {
        const int d = t % 6, fm = t / 6;
        float a = fmb_s[d];
        #pragma unroll
        for (int k = 0; k < 6; ++k) a = fmaf(pos_s[fm * 6 + k], fmw_s[k * 6 + d], a);
        pm[t] = a;
    }
    __syncthreads();

    // pos_up[f,n,d] = sum_m att[b,f,m,n]*pm[f,m,d]  (+ temporal term for f>=1)
    if (t < 120) {
        const int d = t % 6;
        const int t2 = t / 6;
        const int nn = t2 % 4;
        const int f  = t2 / 4;
        float a = 0.0f;
        #pragma unroll
        for (int m = 0; m < 4; ++m)
            a = fmaf(__ldg(att + b * 80 + f * 16 + m * 4 + nn), pm[(f * 4 + m) * 6 + d], a);
        if (f >= 1) {
            a += lmb_s[d];
            #pragma unroll
            for (int k = 0; k < 6; ++k)
                a = fmaf(pos_s[((f - 1) * 4 + nn) * 6 + k], lmw_s[k * 6 + d], a);
        }
        pu[t] = a;
    }
    __syncthreads();

    // feature concat: [nf(6) | df(6) | pos_up(6)] per (f,m) -> 360
    if (t < 360) {
        const int fm = t / 18, c = t % 18;
        float v;
        if (c < 6)       v = g_feats[(b * 20 + fm) * 6 + c];
        else if (c < 12) v = g_feats[(IMG_HALF + b * 20 + fm) * 6 + (c - 6)];
        else             v = pu[fm * 6 + (c - 12)];
        feat[t] = v;
    }
    __syncthreads();

    // MLP layer 1: 360 -> 180, 2-way k-split (360 lanes)
    if (t < 360) {
        const int o  = t % 180;
        const int i0 = (t / 180) * 180;
        float a = 0.0f;
        #pragma unroll 8
        for (int i = 0; i < 180; ++i)
            a = fmaf(feat[i0 + i], __ldg(o1w + (i0 + i) * 180 + o), a);
        p1[t] = a;
    }
    __syncthreads();
    if (t < 180)
        h1[t] = fmaxf(p1[t] + p1[t + 180] + __ldg(o1b + t), 0.0f);
    __syncthreads();

    // MLP layer 2: 180 -> 60, 4-way k-split (240 lanes)
    if (t < 240) {
        const int o  = t % 60;
        const int i0 = (t / 60) * 45;
        float a = 0.0f;
        #pragma unroll
        for (int i = 0; i < 45; ++i)
            a = fmaf(h1[i0 + i], __ldg(o2w + (i0 + i) * 60 + o), a);
        p2[t] = a;
    }
    __syncthreads();
    if (t < 60)
        h2[t] = fmaxf(p2[t] + p2[t + 60] + p2[t + 120] + p2[t + 180] +
                      __ldg(o2b + t), 0.0f);
    __syncthreads();

    // MLP layer 3: 60 -> 6
    if (t < 6) {
        float a = __ldg(o3b + t);
        #pragma unroll
        for (int i = 0; i < 60; ++i)
            a = fmaf(h2[i], __ldg(o3w + i * 6 + t), a);
        out[b * 6 + t] = a;
    }
}

// ---------------------------------------------------------------------------
// Launch
// ---------------------------------------------------------------------------
extern "C" void kernel_launch(void* const* d_in, const int* in_sizes, int n_in,
                              void* d_out, int out_size)
{
    (void)in_sizes; (void)n_in; (void)out_size;

    // raise dynamic-smem limit (non-stream API; no allocation; idempotent)
    cudaFuncSetAttribute(backbone_kernel,
                         cudaFuncAttributeMaxDynamicSharedMemorySize, SMEM_BYTES);

    BBParams P;
    P.nodes  = (const float*)d_in[0];
    P.depths = (const float*)d_in[3];
    P.c1w  = (const float*)d_in[4];   P.c1b  = (const float*)d_in[5];
    P.c2w  = (const float*)d_in[6];   P.c2b  = (const float*)d_in[7];
    P.lw   = (const float*)d_in[8];   P.lb   = (const float*)d_in[9];
    P.dc1w = (const float*)d_in[10];  P.dc1b = (const float*)d_in[11];
    P.dc2w = (const float*)d_in[12];  P.dc2b = (const float*)d_in[13];
    P.dlw  = (const float*)d_in[14];  P.dlb  = (const float*)d_in[15];

    backbone_kernel<<<NIMG, 256, SMEM_BYTES>>>(P);

    head_kernel<<<NSAMP, 512>>>(
        (const float*)d_in[1],  (const float*)d_in[2],
        (const float*)d_in[16], (const float*)d_in[17],
        (const float*)d_in[18], (const float*)d_in[19],
        (const float*)d_in[20], (const float*)d_in[21],
        (const float*)d_in[22], (const float*)d_in[23],
        (const float*)d_in[24], (const float*)d_in[25],
        (float*)d_out);
}

// round 15
// speedup vs baseline: 2.3089x; 2.3089x over previous
#include <cuda_runtime.h>
#include <math.h>

// ---------------------------------------------------------------------------
// Problem constants
// ---------------------------------------------------------------------------
#define NSAMP   32
#define NIMG    1280          // 640 RGB + 640 depth images of [3,224,224]
#define IMG_HALF 640
#define IMG_ELEMS (3*224*224)
#define CH_ELEMS  (224*224)

// per-image 6-float backbone features: [0..640) rgb, [640..1280) depth
__device__ float g_feats[NIMG * 6];

struct BBParams {
    const float* nodes;
    const float* depths;
    const float* c1w;  const float* c1b;  const float* c2w;  const float* c2b;
    const float* lw;   const float* lb;
    const float* dc1w; const float* dc1b; const float* dc2w; const float* dc2b;
    const float* dlw;  const float* dlb;
};

// ---------------------------------------------------------------------------
// Dynamic shared-memory layout (floats) — 16504 floats = 66016 B
// ---------------------------------------------------------------------------
#define STRIP_ROW 228                 // 224 cols + 4 pad
#define STRIP_CH  (7*STRIP_ROW)       // 7 input rows per pool row
#define STRIP_SZ  (3*STRIP_CH)        // 4788
#define SM_STRIP0 0
#define SM_STRIP1 4788
#define CB_ROW    112
#define CB_CH     (3*CB_ROW)          // 3 conv rows per pool row
#define CB_SZ     (3*CB_CH)           // 1008
#define SM_CONV0  9576
#define SM_CONV1  10584
#define IN_ROW    38
#define IN_CH     (37*IN_ROW)
#define SM_INTER  11592               // 3*37*38 = 4218
#define SM_C2     15810               // 324
#define SM_V      16134               // 36
#define SM_W      16170               // 334 weight floats
#define SM_TOTAL  16504
#define SMEM_BYTES (SM_TOTAL*4)

// Bank-conflict swizzle for the strip: logical word w within a row maps to
// physical word w ^ (((w>>5)&1)<<2). Applied identically at store and load.
__device__ __forceinline__ int strip_sw(int w) {
    return w ^ (((w >> 5) & 1) << 2);
}

__device__ __forceinline__ void cp_async16(float* smem_dst, const float* gsrc) {
    unsigned sa = (unsigned)__cvta_generic_to_shared(smem_dst);
    asm volatile("cp.async.cg.shared.global [%0], [%1], 16;" :: "r"(sa), "l"(gsrc));
}
__device__ __forceinline__ void cp_async_commit() {
    asm volatile("cp.async.commit_group;");
}
__device__ __forceinline__ void cp_async_wait_all() {
    asm volatile("cp.async.wait_group 0;");
}

// weight smem sub-offsets (relative to SM_W)
//   w1: [0,81)  b1: [81,84)  w2: [84,111)  b2: [111]  lw: [112,328)  lb: [328,334)

__global__ __launch_bounds__(256)
void backbone_kernel(BBParams P)
{
    extern __shared__ __align__(16) float sm[];

    const int img = blockIdx.x;
    const int tid = threadIdx.x;
    const bool rgb = (img < IMG_HALF);
    const int local = rgb ? img : (img - IMG_HALF);
    const float* input = (rgb ? P.nodes : P.depths) + (size_t)local * IMG_ELEMS;

    // ---- prologue: weights + strip(0) load (all threads), single barrier ----
    {
        const float* w1 = rgb ? P.c1w : P.dc1w;
        const float* b1 = rgb ? P.c1b : P.dc1b;
        const float* w2 = rgb ? P.c2w : P.dc2w;
        const float* b2 = rgb ? P.c2b : P.dc2b;
        const float* lw = rgb ? P.lw  : P.dlw;
        const float* lb = rgb ? P.lb  : P.dlb;
        float* ws = sm + SM_W;
        if (tid < 81)  ws[tid]       = __ldg(w1 + tid);
        if (tid < 3)   ws[81 + tid]  = __ldg(b1 + tid);
        if (tid < 27)  ws[84 + tid]  = __ldg(w2 + tid);
        if (tid == 0)  ws[111]       = __ldg(b2);
        if (tid < 216) ws[112 + tid] = __ldg(lw + tid);
        if (tid < 6)   ws[328 + tid] = __ldg(lb + tid);

        for (int i = tid; i < 3 * 7 * 56; i += 256) {
            const int ch  = i / 392;
            const int rem = i - ch * 392;
            const int r   = rem / 56;
            const int c4  = rem - r * 56;
            cp_async16(sm + SM_STRIP0 + ch * STRIP_CH + r * STRIP_ROW + strip_sw(4 * c4),
                       input + ch * CH_ELEMS + r * 224 + 4 * c4);
        }
        cp_async_commit();
        cp_async_wait_all();
    }
    __syncthreads();

    // ---- stage 1 pipeline: warps 0-2 conv(p); warps 3-7 load(p+1) + pool(p-1)
    for (int p = 0; p < 37; ++p) {
        const float* strip = sm + ((p & 1) ? SM_STRIP1 : SM_STRIP0);
        float*       conv  = sm + ((p & 1) ? SM_CONV1  : SM_CONV0);

        if (tid < 96) {
            // conv1: one warp per conv row; each lane 4 cols x 3 out channels
            const int crow = tid >> 5;
            const int lane = tid & 31;
            const float* ws = sm + SM_W;
            const float b0 = ws[81], b1 = ws[82], b2 = ws[83];
            float4 a0 = make_float4(b0, b0, b0, b0);
            float4 a1 = make_float4(b1, b1, b1, b1);
            float4 a2 = make_float4(b2, b2, b2, b2);

            const int s4 = ((lane >> 2) & 1) << 2;
            const int wA = (8 * lane) ^ s4;
            const int wB = (8 * lane + 4) ^ s4;
            const int wC = (8 * lane + 8) ^ ((((8 * lane + 8) >> 5) & 1) << 2);

            #pragma unroll
            for (int ci = 0; ci < 3; ++ci) {
                const float* sp = strip + ci * STRIP_CH + 2 * crow * STRIP_ROW;
                #pragma unroll
                for (int ky = 0; ky < 3; ++ky) {
                    const float* rp = sp + ky * STRIP_ROW;
                    float4 A = *(const float4*)(rp + wA);
                    float4 B = *(const float4*)(rp + wB);
                    float s8 = rp[wC];

                    const float* wp = ws + ci * 9 + ky * 3;
                    {
                        float u = wp[0], v = wp[1], w = wp[2];
                        a0.x = fmaf(u, A.x, a0.x); a0.x = fmaf(v, A.y, a0.x); a0.x = fmaf(w, A.z, a0.x);
                        a0.y = fmaf(u, A.z, a0.y); a0.y = fmaf(v, A.w, a0.y); a0.y = fmaf(w, B.x, a0.y);
                        a0.z = fmaf(u, B.x, a0.z); a0.z = fmaf(v, B.y, a0.z); a0.z = fmaf(w, B.z, a0.z);
                        a0.w = fmaf(u, B.z, a0.w); a0.w = fmaf(v, B.w, a0.w); a0.w = fmaf(w, s8,  a0.w);
                    }
                    {
                        float u = wp[27], v = wp[28], w = wp[29];
                        a1.x = fmaf(u, A.x, a1.x); a1.x = fmaf(v, A.y, a1.x); a1.x = fmaf(w, A.z, a1.x);
                        a1.y = fmaf(u, A.z, a1.y); a1.y = fmaf(v, A.w, a1.y); a1.y = fmaf(w, B.x, a1.y);
                        a1.z = fmaf(u, B.x, a1.z); a1.z = fmaf(v, B.y, a1.z); a1.z = fmaf(w, B.z, a1.z);
                        a1.w = fmaf(u, B.z, a1.w); a1.w = fmaf(v, B.w, a1.w); a1.w = fmaf(w, s8,  a1.w);
                    }
                    {
                        float u = wp[54], v = wp[55], w = wp[56];
                        a2.x = fmaf(u, A.x, a2.x); a2.x = fmaf(v, A.y, a2.x); a2.x = fmaf(w, A.z, a2.x);
                        a2.y = fmaf(u, A.z, a2.y); a2.y = fmaf(v, A.w, a2.y); a2.y = fmaf(w, B.x, a2.y);
                        a2.z = fmaf(u, B.x, a2.z); a2.z = fmaf(v, B.y, a2.z); a2.z = fmaf(w, B.z, a2.z);
                        a2.w = fmaf(u, B.z, a2.w); a2.w = fmaf(v, B.w, a2.w); a2.w = fmaf(w, s8,  a2.w);
                    }
                }
            }
            if (lane < 28) {
                float* ob = conv + crow * CB_ROW + 4 * lane;
                *(float4*)(ob)             = a0;
                *(float4*)(ob + CB_CH)     = a1;
                *(float4*)(ob + 2 * CB_CH) = a2;
            }
        } else {
            const int lt = tid - 96;               // 0..159
            // prefetch strip(p+1) into the other buffer (fire-and-forget)
            if (p < 36) {
                const int S = 6 * (p + 1);
                float* dst = sm + ((p & 1) ? SM_STRIP0 : SM_STRIP1);
                for (int i = lt; i < 3 * 7 * 56; i += 160) {
                    const int ch  = i / 392;
                    const int rem = i - ch * 392;
                    const int r   = rem / 56;
                    const int c4  = rem - r * 56;
                    cp_async16(dst + ch * STRIP_CH + r * STRIP_ROW + strip_sw(4 * c4),
                               input + ch * CH_ELEMS + (S + r) * 224 + 4 * c4);
                }
                cp_async_commit();
            }
            // pool 3x3 s3 + relu of previous pool row
            if (p > 0 && lt < 111) {
                const int pp = p - 1;
                const int pc = lt % 37;
                const int ch = lt / 37;
                const float* cb = sm + ((pp & 1) ? SM_CONV1 : SM_CONV0) +
                                  ch * CB_CH + 3 * pc;
                float m = cb[0];
                #pragma unroll
                for (int ky = 0; ky < 3; ++ky)
                    #pragma unroll
                    for (int kx = 0; kx < 3; ++kx)
                        m = fmaxf(m, cb[ky * CB_ROW + kx]);
                sm[SM_INTER + ch * IN_CH + pp * IN_ROW + pc] = fmaxf(m, 0.0f);
            }
            if (p < 36) cp_async_wait_all();
        }
        __syncthreads();
    }

    // final pool row (p = 36, convbuf parity 0)
    if (tid < 111) {
        const int pc = tid % 37;
        const int ch = tid / 37;
        const float* cb = sm + SM_CONV0 + ch * CB_CH + 3 * pc;
        float m = cb[0];
        #pragma unroll
        for (int ky = 0; ky < 3; ++ky)
            #pragma unroll
            for (int kx = 0; kx < 3; ++kx)
                m = fmaxf(m, cb[ky * CB_ROW + kx]);
        sm[SM_INTER + ch * IN_CH + 36 * IN_ROW + pc] = fmaxf(m, 0.0f);
    }
    __syncthreads();

    // ---- stage 2: conv2(3->1, 3x3, s2): 18x18 outputs ----
    {
        const float* ws = sm + SM_W;
        for (int t = tid; t < 324; t += 256) {
            const int r = t / 18, c = t % 18;
            float acc = ws[111];
            const float* ip = sm + SM_INTER + (2 * r) * IN_ROW + 2 * c;
            #pragma unroll
            for (int ci = 0; ci < 3; ++ci)
                #pragma unroll
                for (int ky = 0; ky < 3; ++ky)
                    #pragma unroll
                    for (int kx = 0; kx < 3; ++kx)
                        acc = fmaf(ws[84 + ci*9 + ky*3 + kx],
                                   ip[ci * IN_CH + ky * IN_ROW + kx], acc);
            sm[SM_C2 + t] = acc;
        }
    }
    __syncthreads();
    // pool 3x3 s3 + relu -> 6x6 = 36 values
    if (tid < 36) {
        const int y = tid / 6, x = tid % 6;
        const float* cb = sm + SM_C2 + (3 * y) * 18 + 3 * x;
        float m = cb[0];
        #pragma unroll
        for (int ky = 0; ky < 3; ++ky)
            #pragma unroll
            for (int kx = 0; kx < 3; ++kx)
                m = fmaxf(m, cb[ky * 18 + kx]);
        sm[SM_V + tid] = fmaxf(m, 0.0f);
    }
    __syncthreads();
    // linear 36 -> 6
    if (tid < 6) {
        const float* ws = sm + SM_W;
        float acc = ws[328 + tid];
        #pragma unroll
        for (int j = 0; j < 36; ++j)
            acc = fmaf(sm[SM_V + j], ws[112 + j * 6 + tid], acc);
        g_feats[img * 6 + tid] = acc;
    }
}

// ---------------------------------------------------------------------------
// Head: message passing + concat + MLP (360->180->60->6). One CTA per sample.
// ---------------------------------------------------------------------------
__global__ __launch_bounds__(512)
void head_kernel(const float* __restrict__ pos, const float* __restrict__ att,
                 const float* __restrict__ fmw, const float* __restrict__ fmb,
                 const float* __restrict__ lmw, const float* __restrict__ lmb,
                 const float* __restrict__ o1w, const float* __restrict__ o1b,
                 const float* __restrict__ o2w, const float* __restrict__ o2b,
                 const float* __restrict__ o3w, const float* __restrict__ o3b,
                 float* __restrict__ out)
{
    __shared__ float pos_s[120], pm[120], pu[120], feat[360];
    __shared__ float p1[360];          // layer-1 partials (2-way k-split)
    __shared__ float h1[180];
    __shared__ float p2[240];          // layer-2 partials (4-way k-split)
    __shared__ float h2[60];
    __shared__ float fmw_s[36], fmb_s[6], lmw_s[36], lmb_s[6];

    const int b = blockIdx.x;
    const int t = threadIdx.x;

    if (t < 120) pos_s[t] = __ldg(pos + b * 120 + t);
    if (t < 36) { fmw_s[t] = __ldg(fmw + t); lmw_s[t] = __ldg(lmw + t); }
    if (t < 6)  { fmb_s[t] = __ldg(fmb + t); lmb_s[t] = __ldg(lmb + t); }
    __syncthreads();

    // per-frame messages pm[f,m,d] = pos @ fmw + fmb
    if (t < 120) {
        const int d = t % 6, fm = t / 6;
        float a = fmb_s[d];
        #pragma unroll
        for (int k = 0; k < 6; ++k) a = fmaf(pos_s[fm * 6 + k], fmw_s[k * 6 + d], a);
        pm[t] = a;
    }
    __syncthreads();

    // pos_up[f,n,d] = sum_m att[b,f,m,n]*pm[f,m,d]  (+ temporal term for f>=1)
    if (t < 120) {
        const int d = t % 6;
        const int t2 = t / 6;
        const int nn = t2 % 4;
        const int f  = t2 / 4;
        float a = 0.0f;
        #pragma unroll
        for (int m = 0; m < 4; ++m)
            a = fmaf(__ldg(att + b * 80 + f * 16 + m * 4 + nn), pm[(f * 4 + m) * 6 + d], a);
        if (f >= 1) {
            a += lmb_s[d];
            #pragma unroll
            for (int k = 0; k < 6; ++k)
                a = fmaf(pos_s[((f - 1) * 4 + nn) * 6 + k], lmw_s[k * 6 + d], a);
        }
        pu[t] = a;
    }
    __syncthreads();

    // feature concat: [nf(6) | df(6) | pos_up(6)] per (f,m) -> 360
    if (t < 360) {
        const int fm = t / 18, c = t % 18;
        float v;
        if (c < 6)       v = g_feats[(b * 20 + fm) * 6 + c];
        else if (c < 12) v = g_feats[(IMG_HALF + b * 20 + fm) * 6 + (c - 6)];
        else             v = pu[fm * 6 + (c - 12)];
        feat[t] = v;
    }
    __syncthreads();

    // MLP layer 1: 360 -> 180, 2-way k-split (360 lanes)
    if (t < 360) {
        const int o  = t % 180;
        const int i0 = (t / 180) * 180;
        float a = 0.0f;
        #pragma unroll 8
        for (int i = 0; i < 180; ++i)
            a = fmaf(feat[i0 + i], __ldg(o1w + (i0 + i) * 180 + o), a);
        p1[t] = a;
    }
    __syncthreads();
    if (t < 180)
        h1[t] = fmaxf(p1[t] + p1[t + 180] + __ldg(o1b + t), 0.0f);
    __syncthreads();

    // MLP layer 2: 180 -> 60, 4-way k-split (240 lanes)
    if (t < 240) {
        const int o  = t % 60;
        const int i0 = (t / 60) * 45;
        float a = 0.0f;
        #pragma unroll
        for (int i = 0; i < 45; ++i)
            a = fmaf(h1[i0 + i], __ldg(o2w + (i0 + i) * 60 + o), a);
        p2[t] = a;
    }
    __syncthreads();
    if (t < 60)
        h2[t] = fmaxf(p2[t] + p2[t + 60] + p2[t + 120] + p2[t + 180] +
                      __ldg(o2b + t), 0.0f);
    __syncthreads();

    // MLP layer 3: 60 -> 6
    if (t < 6) {
        float a = __ldg(o3b + t);
        #pragma unroll
        for (int i = 0; i < 60; ++i)
            a = fmaf(h2[i], __ldg(o3w + i * 6 + t), a);
        out[b * 6 + t] = a;
    }
}

// ---------------------------------------------------------------------------
// Launch
// ---------------------------------------------------------------------------
extern "C" void kernel_launch(void* const* d_in, const int* in_sizes, int n_in,
                              void* d_out, int out_size)
{
    (void)in_sizes; (void)n_in; (void)out_size;

    // raise dynamic-smem limit (non-stream API; no allocation; idempotent)
    cudaFuncSetAttribute(backbone_kernel,
                         cudaFuncAttributeMaxDynamicSharedMemorySize, SMEM_BYTES);

    BBParams P;
    P.nodes  = (const float*)d_in[0];
    P.depths = (const float*)d_in[3];
    P.c1w  = (const float*)d_in[4];   P.c1b  = (const float*)d_in[5];
    P.c2w  = (const float*)d_in[6];   P.c2b  = (const float*)d_in[7];
    P.lw   = (const float*)d_in[8];   P.lb   = (const float*)d_in[9];
    P.dc1w = (const float*)d_in[10];  P.dc1b = (const float*)d_in[11];
    P.dc2w = (const float*)d_in[12];  P.dc2b = (const float*)d_in[13];
    P.dlw  = (const float*)d_in[14];  P.dlb  = (const float*)d_in[15];

    backbone_kernel<<<NIMG, 256, SMEM_BYTES>>>(P);

    head_kernel<<<NSAMP, 512>>>(
        (const float*)d_in[1],  (const float*)d_in[2],
        (const float*)d_in[16], (const float*)d_in[17],
        (const float*)d_in[18], (const float*)d_in[19],
        (const float*)d_in[20], (const float*)d_in[21],
        (const float*)d_in[22], (const float*)d_in[23],
        (const float*)d_in[24], (const float*)d_in[25],
        (float*)d_out);
}